// round 3
// baseline (speedup 1.0000x reference)
#include <cuda_runtime.h>
#include <cstddef>

// Problem constants
#define N_BATCH   32768
#define N_EMBED   1024
#define N_HEADS   8
#define HD        128
#define N_CODES   1024

#define ZQ_ELEMS  ((size_t)N_BATCH * N_EMBED)          // 33,554,432
#define IDX_ELEMS ((size_t)N_BATCH * N_HEADS)          // 262,144

// Tiling
#define TILE_B 64
#define TILE_C 64
#define NTHREADS 256
#define SPITCH 68   // smem row pitch (floats), multiple of 4 for float4

#define REFINE_GAP 2.0e-4f

// smem layout (floats)
#define SM_ZS    0
#define SM_CS    (SM_ZS + 128*SPITCH)
#define SM_ZSQ   (SM_CS + 128*SPITCH)
#define SM_CSQ   (SM_ZSQ + 64)
#define SM_REDV  (SM_CSQ + 64)
#define SM_REDI  (SM_REDV + 64*16)
#define SM_REDV2 (SM_REDI + 64*16)
#define SM_IDXS  (SM_REDV2 + 64*16)
#define SM_TOTAL (SM_IDXS + 64)
#define SMEM_BYTES (SM_TOTAL * 4)

__global__ __launch_bounds__(NTHREADS, 2)
void vq_kernel(const float* __restrict__ z, const float* __restrict__ cb,
               float* __restrict__ out)
{
    float* zq_out   = out;
    float* idx_out  = out + ZQ_ELEMS;
    float* dist_out = out + ZQ_ELEMS + IDX_ELEMS;

    const int h  = blockIdx.y;
    const int b0 = blockIdx.x * TILE_B;
    const int tid = threadIdx.x;
    const int tx = tid & 15;
    const int ty = tid >> 4;

    extern __shared__ float sm[];
    float* zs    = sm + SM_ZS;
    float* cs    = sm + SM_CS;
    float* zsq   = sm + SM_ZSQ;
    float* csq   = sm + SM_CSQ;
    float* redv  = sm + SM_REDV;
    int*   redi  = (int*)(sm + SM_REDI);
    float* redv2 = sm + SM_REDV2;
    int*   idxs  = (int*)(sm + SM_IDXS);

    __shared__ int nflag;
    __shared__ int flaglist[64];

    // ---- Load z tile (64 rows x 128 dims) transposed into smem ----
    #pragma unroll
    for (int e = tid; e < TILE_B * HD; e += NTHREADS) {
        int r = e >> 7;
        int d = e & 127;
        zs[d * SPITCH + r] = z[(size_t)(b0 + r) * N_EMBED + h * HD + d];
    }
    __syncthreads();
    if (tid < TILE_B) {
        float s = 0.f;
        #pragma unroll 8
        for (int k = 0; k < HD; k++) { float v = zs[k * SPITCH + tid]; s += v * v; }
        zsq[tid] = s;
    }
    if (tid == 0) nflag = 0;

    // per-thread running min1/min2 (min2 = second smallest seen by this thread)
    float m1[4] = {3.4e38f, 3.4e38f, 3.4e38f, 3.4e38f};
    float m2[4] = {3.4e38f, 3.4e38f, 3.4e38f, 3.4e38f};
    int   i1[4] = {0, 0, 0, 0};

    for (int kt = 0; kt < N_CODES / TILE_C; kt++) {
        const int cbase = kt * TILE_C;

        __syncthreads();
        #pragma unroll
        for (int e = tid; e < TILE_C * HD; e += NTHREADS) {
            int c = e >> 7;
            int d = e & 127;
            cs[d * SPITCH + c] = cb[((size_t)h * N_CODES + cbase + c) * HD + d];
        }
        __syncthreads();
        if (tid < TILE_C) {
            float s = 0.f;
            #pragma unroll 8
            for (int k = 0; k < HD; k++) { float v = cs[k * SPITCH + tid]; s += v * v; }
            csq[tid] = s;
        }
        __syncthreads();

        // ---- 64x64x128 fp32 GEMM, 4x4 per thread ----
        float acc[4][4];
        #pragma unroll
        for (int i = 0; i < 4; i++)
            #pragma unroll
            for (int j = 0; j < 4; j++) acc[i][j] = 0.f;

        #pragma unroll 4
        for (int k = 0; k < HD; k++) {
            float4 a = *(const float4*)&zs[k * SPITCH + ty * 4];
            float4 b = *(const float4*)&cs[k * SPITCH + tx * 4];
            acc[0][0] += a.x * b.x; acc[0][1] += a.x * b.y; acc[0][2] += a.x * b.z; acc[0][3] += a.x * b.w;
            acc[1][0] += a.y * b.x; acc[1][1] += a.y * b.y; acc[1][2] += a.y * b.z; acc[1][3] += a.y * b.w;
            acc[2][0] += a.z * b.x; acc[2][1] += a.z * b.y; acc[2][2] += a.z * b.z; acc[2][3] += a.z * b.w;
            acc[3][0] += a.w * b.x; acc[3][1] += a.w * b.y; acc[3][2] += a.w * b.z; acc[3][3] += a.w * b.w;
        }

        // ---- Epilogue: distances + running min1/min2 ----
        #pragma unroll
        for (int i = 0; i < 4; i++) {
            const int r = ty * 4 + i;
            const float zq2 = zsq[r];
            float dv[4];
            #pragma unroll
            for (int j = 0; j < 4; j++) {
                float t = zq2 + csq[tx * 4 + j];
                dv[j] = fmaf(-2.0f, acc[i][j], t);
            }
            *(float4*)&dist_out[((size_t)(b0 + r) * N_HEADS + h) * N_CODES + cbase + tx * 4]
                = make_float4(dv[0], dv[1], dv[2], dv[3]);
            #pragma unroll
            for (int j = 0; j < 4; j++) {
                float v = dv[j];
                if (v < m1[i]) { m2[i] = m1[i]; m1[i] = v; i1[i] = cbase + tx * 4 + j; }
                else if (v < m2[i]) { m2[i] = v; }
            }
        }
    }

    // ---- Cross-thread argmin reduction (16 tx per row) ----
    #pragma unroll
    for (int i = 0; i < 4; i++) {
        int r = ty * 4 + i;
        redv [r * 16 + tx] = m1[i];
        redi [r * 16 + tx] = i1[i];
        redv2[r * 16 + tx] = m2[i];
    }
    __syncthreads();
    if (tid < TILE_B) {
        // first-occurrence global min (lower tx == lower k within a tile)
        float bv = redv[tid * 16];
        int   bi = redi[tid * 16];
        int   bt = 0;
        #pragma unroll
        for (int t = 1; t < 16; t++) {
            float v = redv[tid * 16 + t];
            if (v < bv) { bv = v; bi = redi[tid * 16 + t]; bt = t; }
        }
        // global second-min
        float g2 = redv2[tid * 16 + bt];
        #pragma unroll
        for (int t = 0; t < 16; t++) {
            if (t != bt) {
                float v = redv[tid * 16 + t];
                if (v < g2) g2 = v;
            }
        }
        idxs[tid] = bi;
        if (g2 - bv < REFINE_GAP) {
            int slot = atomicAdd(&nflag, 1);
            flaglist[slot] = tid;
        }
    }
    __syncthreads();

    // ---- fp64 refinement for near-tie rows (rare) ----
    const int nf = nflag;
    for (int f = 0; f < nf; f++) {
        const int r = flaglist[f];
        const float zq2 = zsq[r];
        float bestv = 3.4e38f;
        int   bestk = 0x7fffffff;
        #pragma unroll
        for (int kk = 0; kk < 4; kk++) {
            const int k = tid + kk * NTHREADS;
            const float4* c4 = (const float4*)(cb + ((size_t)h * N_CODES + k) * HD);
            double dot = 0.0, cs2 = 0.0;
            #pragma unroll 8
            for (int q = 0; q < HD / 4; q++) {
                float4 cv = c4[q];
                double c0 = (double)cv.x, c1 = (double)cv.y, c2 = (double)cv.z, c3 = (double)cv.w;
                double z0 = (double)zs[(q*4+0) * SPITCH + r];
                double z1 = (double)zs[(q*4+1) * SPITCH + r];
                double z2 = (double)zs[(q*4+2) * SPITCH + r];
                double z3 = (double)zs[(q*4+3) * SPITCH + r];
                dot += z0*c0 + z1*c1 + z2*c2 + z3*c3;
                cs2 += c0*c0 + c1*c1 + c2*c2 + c3*c3;
            }
            float dotf = (float)dot;
            float csqf = (float)cs2;
            float t = zq2 + csqf;                 // fl(z_sq + c_sq)
            float d = fmaf(-2.0f, dotf, t);       // fl(t - 2*dot), 2*dot exact
            if (d < bestv || (d == bestv && k < bestk)) { bestv = d; bestk = k; }
        }
        redv[tid] = bestv;
        redi[tid] = bestk;
        __syncthreads();
        for (int s = NTHREADS / 2; s > 0; s >>= 1) {
            if (tid < s) {
                float v2 = redv[tid + s]; int k2 = redi[tid + s];
                float v1 = redv[tid];     int k1 = redi[tid];
                if (v2 < v1 || (v2 == v1 && k2 < k1)) { redv[tid] = v2; redi[tid] = k2; }
            }
            __syncthreads();
        }
        if (tid == 0) idxs[r] = redi[0];
        __syncthreads();
    }

    // ---- write indices ----
    if (tid < TILE_B) {
        idx_out[(size_t)(b0 + tid) * N_HEADS + h] = (float)idxs[tid];
    }
    __syncthreads();

    // ---- z_q gather: copy selected codebook rows (L2-hot) ----
    const float4* cb4 = (const float4*)cb;
    float4* zq4 = (float4*)zq_out;
    #pragma unroll
    for (int e = tid; e < TILE_B * (HD / 4); e += NTHREADS) {
        int r = e >> 5;
        int q = e & 31;
        int c = idxs[r];
        zq4[((size_t)(b0 + r) * N_EMBED + h * HD) / 4 + q] =
            cb4[((size_t)h * N_CODES + c) * (HD / 4) + q];
    }
}

extern "C" void kernel_launch(void* const* d_in, const int* in_sizes, int n_in,
                              void* d_out, int out_size)
{
    const float* z  = (const float*)d_in[0];   // [32768, 1024]
    const float* cb = (const float*)d_in[1];   // [8, 1024, 128]
    float* out = (float*)d_out;                // [z_q | indices | distances]

    cudaFuncSetAttribute(vq_kernel, cudaFuncAttributeMaxDynamicSharedMemorySize, SMEM_BYTES);

    dim3 grid(N_BATCH / TILE_B, N_HEADS);
    vq_kernel<<<grid, NTHREADS, SMEM_BYTES>>>(z, cb, out);
}

// round 6
// speedup vs baseline: 1.1217x; 1.1217x over previous
#include <cuda_runtime.h>
#include <cstddef>

// Problem constants
#define N_BATCH   32768
#define N_EMBED   1024
#define N_HEADS   8
#define HD        128
#define N_CODES   1024

#define ZQ_ELEMS  ((size_t)N_BATCH * N_EMBED)
#define IDX_ELEMS ((size_t)N_BATCH * N_HEADS)

// Tiling: 128x128 tile, 256 threads, 8x8 per thread
#define TILE_B 128
#define TILE_C 128
#define NTHREADS 256
#define SPITCH 132   // smem row pitch in floats (mult of 4 for float4 alignment)

#define REFINE_GAP 2.0e-4f

// smem layout (floats)
#define SM_ZS    0
#define SM_CS    (SM_ZS + HD*SPITCH)
#define SM_ZSQ   (SM_CS + HD*SPITCH)
#define SM_CSQ   (SM_ZSQ + TILE_B)
#define SM_REDV  (SM_CSQ + TILE_C)
#define SM_REDI  (SM_REDV + TILE_B*16)
#define SM_REDV2 (SM_REDI + TILE_B*16)
#define SM_IDXS  (SM_REDV2 + TILE_B*16)
#define SM_TOTAL (SM_IDXS + TILE_B)
#define SMEM_BYTES (SM_TOTAL * 4)

__global__ __launch_bounds__(NTHREADS, 1)
void vq_kernel(const float* __restrict__ z, const float* __restrict__ cb,
               float* __restrict__ out)
{
    float* zq_out   = out;
    float* idx_out  = out + ZQ_ELEMS;
    float* dist_out = out + ZQ_ELEMS + IDX_ELEMS;

    const int h  = blockIdx.y;
    const int b0 = blockIdx.x * TILE_B;
    const int tid = threadIdx.x;
    const int tx = tid & 15;     // column group
    const int ty = tid >> 4;     // row group (0..15)

    extern __shared__ float sm[];
    float* zs    = sm + SM_ZS;   // [k][row]  transposed z tile
    float* cs    = sm + SM_CS;   // [k][code] transposed code tile
    float* zsq   = sm + SM_ZSQ;
    float* csq   = sm + SM_CSQ;
    float* redv  = sm + SM_REDV;
    int*   redi  = (int*)(sm + SM_REDI);
    float* redv2 = sm + SM_REDV2;
    int*   idxs  = (int*)(sm + SM_IDXS);

    __shared__ int nflag;
    __shared__ int flaglist[TILE_B];

    // ---- Load z tile (128 rows x 128 dims) transposed into smem ----
    #pragma unroll
    for (int s = 0; s < TILE_B * HD / NTHREADS; s++) {
        int e = tid + s * NTHREADS;
        int r = e >> 7;
        int d = e & 127;
        zs[d * SPITCH + r] = z[(size_t)(b0 + r) * N_EMBED + h * HD + d];
    }
    __syncthreads();
    if (tid < TILE_B) {
        float s = 0.f;
        #pragma unroll 8
        for (int k = 0; k < HD; k++) { float v = zs[k * SPITCH + tid]; s += v * v; }
        zsq[tid] = s;
    }
    if (tid == 0) nflag = 0;

    // Row indices owned: r = ty*8 + i (i<8)
    // Col indices owned: c = 4*tx + j (j<4), c = 64 + 4*tx + (j-4) (j>=4)

    float m1[8], m2[8];
    int   i1[8];
    #pragma unroll
    for (int i = 0; i < 8; i++) { m1[i] = 3.4e38f; m2[i] = 3.4e38f; i1[i] = 0; }

    for (int kt = 0; kt < N_CODES / TILE_C; kt++) {
        const int cbase = kt * TILE_C;

        __syncthreads();
        // load c tile transposed: [k][c]
        #pragma unroll
        for (int s = 0; s < TILE_C * HD / NTHREADS; s++) {
            int e = tid + s * NTHREADS;
            int c = e >> 7;
            int d = e & 127;
            cs[d * SPITCH + c] = cb[((size_t)h * N_CODES + cbase + c) * HD + d];
        }
        __syncthreads();
        if (tid < TILE_C) {
            float s = 0.f;
            #pragma unroll 8
            for (int k = 0; k < HD; k++) { float v = cs[k * SPITCH + tid]; s += v * v; }
            csq[tid] = s;
        }
        __syncthreads();

        // ---- 128x128x128 fp32 GEMM, 8x8 per thread ----
        float acc[8][8];
        #pragma unroll
        for (int i = 0; i < 8; i++)
            #pragma unroll
            for (int j = 0; j < 8; j++) acc[i][j] = 0.f;

        #pragma unroll 4
        for (int k = 0; k < HD; k++) {
            const float* zrow = &zs[k * SPITCH];
            const float* crow = &cs[k * SPITCH];
            float4 a0 = *(const float4*)&zrow[ty * 8];
            float4 a1 = *(const float4*)&zrow[ty * 8 + 4];
            float4 bl = *(const float4*)&crow[tx * 4];
            float4 bh = *(const float4*)&crow[64 + tx * 4];
            float a[8] = {a0.x, a0.y, a0.z, a0.w, a1.x, a1.y, a1.z, a1.w};
            float b[8] = {bl.x, bl.y, bl.z, bl.w, bh.x, bh.y, bh.z, bh.w};
            #pragma unroll
            for (int i = 0; i < 8; i++)
                #pragma unroll
                for (int j = 0; j < 8; j++)
                    acc[i][j] += a[i] * b[j];
        }

        // ---- Epilogue: distances + running min1/min2 ----
        #pragma unroll
        for (int i = 0; i < 8; i++) {
            const int r = ty * 8 + i;
            const float zq2 = zsq[r];
            float dv[8];
            #pragma unroll
            for (int j = 0; j < 4; j++) {
                float t = zq2 + csq[tx * 4 + j];
                dv[j] = fmaf(-2.0f, acc[i][j], t);
            }
            #pragma unroll
            for (int j = 0; j < 4; j++) {
                float t = zq2 + csq[64 + tx * 4 + j];
                dv[4 + j] = fmaf(-2.0f, acc[i][4 + j], t);
            }
            float* drow = &dist_out[((size_t)(b0 + r) * N_HEADS + h) * N_CODES + cbase];
            *(float4*)&drow[tx * 4]      = make_float4(dv[0], dv[1], dv[2], dv[3]);
            *(float4*)&drow[64 + tx * 4] = make_float4(dv[4], dv[5], dv[6], dv[7]);
            #pragma unroll
            for (int j = 0; j < 8; j++) {
                int c = cbase + ((j < 4) ? (tx * 4 + j) : (64 + tx * 4 + j - 4));
                float v = dv[j];
                // process in ascending c within this thread: j order matches ascending c
                if (v < m1[i]) { m2[i] = m1[i]; m1[i] = v; i1[i] = c; }
                else if (v < m2[i]) { m2[i] = v; }
            }
        }
    }

    // NOTE on first-occurrence semantics: within a thread, cols visited in
    // ascending c per tile and tiles ascend, strict < keeps the first.
    // Across tx threads, the reduction below scans t ascending; for j<4 cols the
    // owner's c ascends with tx, for the +64 block too — any exact tie between
    // the two j-groups of different tx is resolved by the fp64 refinement path
    // (exact ties have gap 0 < REFINE_GAP).

    #pragma unroll
    for (int i = 0; i < 8; i++) {
        int r = ty * 8 + i;
        redv [r * 16 + tx] = m1[i];
        redi [r * 16 + tx] = i1[i];
        redv2[r * 16 + tx] = m2[i];
    }
    __syncthreads();
    if (tid < TILE_B) {
        float bv = redv[tid * 16];
        int   bi = redi[tid * 16];
        int   bt = 0;
        #pragma unroll
        for (int t = 1; t < 16; t++) {
            float v = redv[tid * 16 + t];
            int   c = redi[tid * 16 + t];
            if (v < bv || (v == bv && c < bi)) { bv = v; bi = c; bt = t; }
        }
        float g2 = redv2[tid * 16 + bt];
        #pragma unroll
        for (int t = 0; t < 16; t++) {
            if (t != bt) {
                float v = redv[tid * 16 + t];
                if (v < g2) g2 = v;
            }
        }
        idxs[tid] = bi;
        if (g2 - bv < REFINE_GAP) {
            int slot = atomicAdd(&nflag, 1);
            flaglist[slot] = tid;
        }
    }
    __syncthreads();

    // ---- fp64 refinement for near-tie rows (rare) ----
    const int nf = nflag;
    for (int f = 0; f < nf; f++) {
        const int r = flaglist[f];
        const float zq2 = zsq[r];
        float bestv = 3.4e38f;
        int   bestk = 0x7fffffff;
        #pragma unroll
        for (int kk = 0; kk < 4; kk++) {
            const int k = tid + kk * NTHREADS;
            const float4* c4 = (const float4*)(cb + ((size_t)h * N_CODES + k) * HD);
            double dot = 0.0, cs2 = 0.0;
            #pragma unroll 8
            for (int q = 0; q < HD / 4; q++) {
                float4 cv = c4[q];
                double c0 = (double)cv.x, c1 = (double)cv.y, c2 = (double)cv.z, c3 = (double)cv.w;
                double z0 = (double)zs[(q*4+0) * SPITCH + r];
                double z1 = (double)zs[(q*4+1) * SPITCH + r];
                double z2 = (double)zs[(q*4+2) * SPITCH + r];
                double z3 = (double)zs[(q*4+3) * SPITCH + r];
                dot += z0*c0 + z1*c1 + z2*c2 + z3*c3;
                cs2 += c0*c0 + c1*c1 + c2*c2 + c3*c3;
            }
            float dotf = (float)dot;
            float csqf = (float)cs2;
            float t = zq2 + csqf;
            float d = fmaf(-2.0f, dotf, t);
            if (d < bestv || (d == bestv && k < bestk)) { bestv = d; bestk = k; }
        }
        redv[tid] = bestv;
        redi[tid] = bestk;
        __syncthreads();
        for (int s = NTHREADS / 2; s > 0; s >>= 1) {
            if (tid < s) {
                float v2 = redv[tid + s]; int k2 = redi[tid + s];
                float v1 = redv[tid];     int k1 = redi[tid];
                if (v2 < v1 || (v2 == v1 && k2 < k1)) { redv[tid] = v2; redi[tid] = k2; }
            }
            __syncthreads();
        }
        if (tid == 0) idxs[r] = redi[0];
        __syncthreads();
    }

    // ---- write indices ----
    if (tid < TILE_B) {
        idx_out[(size_t)(b0 + tid) * N_HEADS + h] = (float)idxs[tid];
    }
    __syncthreads();

    // ---- z_q gather ----
    const float4* cb4 = (const float4*)cb;
    float4* zq4 = (float4*)zq_out;
    #pragma unroll
    for (int s = 0; s < TILE_B * (HD / 4) / NTHREADS; s++) {
        int e = tid + s * NTHREADS;
        int r = e >> 5;
        int q = e & 31;
        int c = idxs[r];
        zq4[(size_t)(b0 + r) * (N_EMBED / 4) + h * (HD / 4) + q] =
            cb4[((size_t)h * N_CODES + c) * (HD / 4) + q];
    }
}

extern "C" void kernel_launch(void* const* d_in, const int* in_sizes, int n_in,
                              void* d_out, int out_size)
{
    const float* z  = (const float*)d_in[0];   // [32768, 1024]
    const float* cb = (const float*)d_in[1];   // [8, 1024, 128]
    float* out = (float*)d_out;

    cudaFuncSetAttribute(vq_kernel, cudaFuncAttributeMaxDynamicSharedMemorySize, SMEM_BYTES);

    dim3 grid(N_BATCH / TILE_B, N_HEADS);
    vq_kernel<<<grid, NTHREADS, SMEM_BYTES>>>(z, cb, out);
}

// round 9
// speedup vs baseline: 2.3610x; 2.1048x over previous
#include <cuda_runtime.h>
#include <cuda_bf16.h>
#include <cstdint>
#include <cstddef>

// ---------------- arch gate ----------------
// tcgen05 is only emittable when nvcc compiles an arch-specific (sm_103a) or
// family-specific pass. Under plain compute_103 the macros are undefined and
// the tcgen05 kernel compiles to an empty body; the fp32 kernel takes over.
#if defined(__CUDA_ARCH__) && (defined(__CUDA_ARCH_FEAT_SM103_ALL) || defined(__CUDA_ARCH_SPECIFIC__) || defined(__CUDA_ARCH_FAMILY_SPECIFIC__))
#define TCOK 1
#else
#define TCOK 0
#endif

// ---------------- Problem constants ----------------
#define N_BATCH 32768
#define N_EMBED 1024
#define N_HEADS 8
#define HD 128
#define N_CODES 1024
#define ZQ_ELEMS ((size_t)N_BATCH*N_EMBED)
#define IDX_ELEMS ((size_t)N_BATCH*N_HEADS)

#define TILE_B 128
#define CHUNK 128
#define NCHUNKS 8
#define NTHREADS 256
#define REFINE_GAP 2.0e-4f

#define TILE_BYTES 32768   // one 128x128 bf16 tile image

// idesc: F32 accum, BF16 a/b, M=128, N=128
#define IDESC 0x08200490u

// ---------------- smem offsets (bytes), tcgen05 kernel ----------------
#define SO_AHI    0
#define SO_ALO    32768
#define SO_B0     65536      // [hi 32768 | lo 32768]
#define SO_B1     131072
#define SO_T      196608     // 32*129*4 = 16512 transpose buf (overlaid later)
#define SO_CSQ    213120     // 1024 floats
#define SO_ZSQ    217216     // 128 floats
#define SO_IDX    218752     // 128 ints
#define SO_FLAG   219264     // 128 ints
#define SO_MBAR   219776     // 2 x 8B
#define SO_TMEMPTR 219792
#define SO_NFLAG  219796
#define SMEM_BYTES 219808

// ---------------- scratch (device globals) ----------------
__device__ __align__(16) unsigned char g_cb_tiles[N_HEADS * NCHUNKS * 2 * TILE_BYTES];
__device__ float g_csq[N_HEADS * N_CODES];

// ---------------- helpers ----------------
__device__ __forceinline__ uint32_t smem_u32(const void* p) {
    uint32_t a;
    asm("{ .reg .u64 t; cvta.to.shared.u64 t, %1; cvt.u32.u64 %0, t; }" : "=r"(a) : "l"(p));
    return a;
}

// blocked SW128 layout for a 128x128 bf16 K-major tile (atoms 8 rows x 64 bf16,
// 16 atom-rows, 2 atom-cols, atom_off = atom_row + atom_col*16) + swizzle.
__device__ __forceinline__ int tile_off128(int row, int d) {
    int off = (((row >> 3) + ((d >> 6) << 4)) << 10) + ((row & 7) << 7) + ((d & 63) << 1);
    return off ^ ((off >> 3) & 0x70);
}

#if TCOK
__device__ __forceinline__ uint32_t elect_one() {
    uint32_t pred;
    asm volatile("{\n\t.reg .pred p;\n\telect.sync _|p, 0xFFFFFFFF;\n\tselp.b32 %0, 1, 0, p;\n\t}" : "=r"(pred));
    return pred;
}

// smem descriptor: SW128, version=1, SBO=64, LBO=1
__device__ __forceinline__ uint64_t make_desc(uint32_t smem_addr) {
    return ((uint64_t)2 << 61) | ((uint64_t)1 << 46) | ((uint64_t)64 << 32) | ((uint64_t)1 << 16)
         | ((uint64_t)(smem_addr >> 4) & 0x3FFF);
}

__device__ __forceinline__ void mma_f16_ss(uint32_t d_tmem, uint64_t a_desc, uint64_t b_desc,
                                           uint32_t idesc, uint32_t accum) {
    asm volatile(
        "{\n\t.reg .pred p;\n\tsetp.ne.u32 p, %4, 0;\n\t"
        "tcgen05.mma.cta_group::1.kind::f16 [%0], %1, %2, %3, {%5,%5,%5,%5}, p;\n\t}"
        :: "r"(d_tmem), "l"(a_desc), "l"(b_desc), "r"(idesc), "r"(accum), "r"(0u) : "memory");
}

__device__ __forceinline__ void mbar_init(uint32_t a, uint32_t cnt) {
    asm volatile("mbarrier.init.shared.b64 [%0], %1;" :: "r"(a), "r"(cnt) : "memory");
}
__device__ __forceinline__ void mbar_wait(uint32_t a, uint32_t parity) {
    asm volatile(
        "{\n\t.reg .pred P1;\n\t"
        "WAIT_LOOP_%=:\n\t"
        "mbarrier.try_wait.parity.acquire.cta.shared::cta.b64 P1, [%0], %1, 0x989680;\n\t"
        "@P1 bra.uni WAIT_DONE_%=;\n\t"
        "bra.uni WAIT_LOOP_%=;\n\t"
        "WAIT_DONE_%=:\n\t}"
        :: "r"(a), "r"(parity) : "memory");
}
__device__ __forceinline__ void cp_async16(uint32_t dst, const void* src) {
    asm volatile("cp.async.cg.shared.global [%0], [%1], 16;" :: "r"(dst), "l"(src) : "memory");
}
__device__ __forceinline__ void cp_commit() { asm volatile("cp.async.commit_group;" ::: "memory"); }
__device__ __forceinline__ void cp_wait1()  { asm volatile("cp.async.wait_group 1;" ::: "memory"); }
__device__ __forceinline__ void cp_wait0()  { asm volatile("cp.async.wait_group 0;" ::: "memory"); }

#define T05_FENCE_AFTER()  asm volatile("tcgen05.fence::after_thread_sync;" ::: "memory")
#define T05_FENCE_BEFORE() asm volatile("tcgen05.fence::before_thread_sync;" ::: "memory")
#define T05_WAIT_LD()      asm volatile("tcgen05.wait::ld.sync.aligned;" ::: "memory")
#define FENCE_PROXY()      asm volatile("fence.proxy.async.shared::cta;" ::: "memory")

#define LDTM_X32(r, addr) \
    asm volatile( \
        "tcgen05.ld.sync.aligned.32x32b.x32.b32 " \
        "{%0, %1, %2, %3, %4, %5, %6, %7, %8, %9, %10, %11, %12, %13, %14, %15, " \
        " %16, %17, %18, %19, %20, %21, %22, %23, %24, %25, %26, %27, %28, %29, %30, %31}, [%32];" \
        : "=r"((r)[0]),  "=r"((r)[1]),  "=r"((r)[2]),  "=r"((r)[3]), \
          "=r"((r)[4]),  "=r"((r)[5]),  "=r"((r)[6]),  "=r"((r)[7]), \
          "=r"((r)[8]),  "=r"((r)[9]),  "=r"((r)[10]), "=r"((r)[11]), \
          "=r"((r)[12]), "=r"((r)[13]), "=r"((r)[14]), "=r"((r)[15]), \
          "=r"((r)[16]), "=r"((r)[17]), "=r"((r)[18]), "=r"((r)[19]), \
          "=r"((r)[20]), "=r"((r)[21]), "=r"((r)[22]), "=r"((r)[23]), \
          "=r"((r)[24]), "=r"((r)[25]), "=r"((r)[26]), "=r"((r)[27]), \
          "=r"((r)[28]), "=r"((r)[29]), "=r"((r)[30]), "=r"((r)[31]) \
        : "r"(addr))
#endif // TCOK

// ---------------- prep kernels (tcgen05 path only) ----------------
__global__ void prep_cb_kernel(const float* __restrict__ cb) {
#if TCOK
    const int h = blockIdx.x >> 3;
    const int chunk = blockIdx.x & 7;
    unsigned char* base = g_cb_tiles + ((size_t)(h * NCHUNKS + chunk) * 2) * TILE_BYTES;
    for (int e = threadIdx.x; e < CHUNK * HD; e += blockDim.x) {
        int row = e >> 7;
        int d   = e & 127;
        float f = cb[((size_t)h * N_CODES + chunk * CHUNK + row) * HD + d];
        __nv_bfloat16 hi = __float2bfloat16(f);
        __nv_bfloat16 lo = __float2bfloat16(f - __bfloat162float(hi));
        int off = tile_off128(row, d);
        *(__nv_bfloat16*)(base + off) = hi;
        *(__nv_bfloat16*)(base + TILE_BYTES + off) = lo;
    }
#endif
}

__global__ void prep_csq_kernel(const float* __restrict__ cb) {
#if TCOK
    int g = blockIdx.x * blockDim.x + threadIdx.x;
    if (g >= N_HEADS * N_CODES) return;
    const float4* row = (const float4*)(cb + (size_t)g * HD);
    double s = 0.0;
    #pragma unroll 8
    for (int q = 0; q < HD / 4; q++) {
        float4 v = row[q];
        s += (double)v.x * v.x + (double)v.y * v.y + (double)v.z * v.z + (double)v.w * v.w;
    }
    g_csq[g] = (float)s;
#endif
}

// ---------------- tcgen05 main kernel ----------------
__global__ __launch_bounds__(NTHREADS, 1)
void vq_main_kernel(const float* __restrict__ z, const float* __restrict__ cb,
                    float* __restrict__ out)
{
#if TCOK
    float* zq_out   = out;
    float* idx_out  = out + ZQ_ELEMS;
    float* dist_out = out + ZQ_ELEMS + IDX_ELEMS;

    const int h  = blockIdx.y;
    const int b0 = blockIdx.x * TILE_B;
    const int tid  = threadIdx.x;
    const int wid  = tid >> 5;
    const int lane = tid & 31;
    const int wgid = wid >> 2;          // which 64-col half
    const int subp = wid & 3;           // TMEM subpartition
    const int myrow = subp * 32 + lane; // z row within tile

    extern __shared__ char sm[];
    const uint32_t smb = smem_u32(sm);
    float* csq_s = (float*)(sm + SO_CSQ);
    float* zsq_s = (float*)(sm + SO_ZSQ);
    int*   idxs  = (int*)(sm + SO_IDX);
    int*   flagl = (int*)(sm + SO_FLAG);
    int*   nflag = (int*)(sm + SO_NFLAG);
    float* Tb    = (float*)(sm + SO_T);
    const uint32_t mbar0 = smb + SO_MBAR;
    const uint32_t mbar1 = smb + SO_MBAR + 8;

    if (tid == 0) { mbar_init(mbar0, 1); mbar_init(mbar1, 1); *nflag = 0; }
    if (wid == 0) {
        asm volatile("tcgen05.alloc.cta_group::1.sync.aligned.shared::cta.b32 [%0], %1;"
                     :: "r"(smb + SO_TMEMPTR), "r"(256u) : "memory");
        asm volatile("tcgen05.relinquish_alloc_permit.cta_group::1.sync.aligned;");
    }

    // ---- A convert: z rows -> split bf16, swizzled tiles ----
    {
        const int r = tid >> 1;
        const int half = tid & 1;
        const float2* zr = (const float2*)(z + (size_t)(b0 + r) * N_EMBED + h * HD + half * 64);
        #pragma unroll 8
        for (int t = 0; t < 32; t++) {
            float2 v = zr[t];
            int d = half * 64 + t * 2;
            __nv_bfloat16 hx = __float2bfloat16(v.x);
            __nv_bfloat16 hy = __float2bfloat16(v.y);
            __nv_bfloat162 hi2; hi2.x = hx; hi2.y = hy;
            __nv_bfloat162 lo2;
            lo2.x = __float2bfloat16(v.x - __bfloat162float(hx));
            lo2.y = __float2bfloat16(v.y - __bfloat162float(hy));
            int off = tile_off128(r, d);
            *(__nv_bfloat162*)(sm + SO_AHI + off) = hi2;
            *(__nv_bfloat162*)(sm + SO_ALO + off) = lo2;
        }
    }
    #pragma unroll
    for (int i = tid; i < N_CODES; i += NTHREADS) csq_s[i] = g_csq[h * N_CODES + i];

    // ---- zsq: EXACT R3 arithmetic — sequential ascending-k fp32 FMA chain.
    // The reference quantizes distances to ulp(128)=1.5e-5; near-tie rows are
    // decided by the exact bits of zsq. This order passed in R2+R3.
    if (tid < TILE_B) {
        const float4* zr = (const float4*)(z + (size_t)(b0 + tid) * N_EMBED + h * HD);
        float s = 0.f;
        #pragma unroll 8
        for (int q = 0; q < HD / 4; q++) {
            float4 v = zr[q];
            s = fmaf(v.x, v.x, s);
            s = fmaf(v.y, v.y, s);
            s = fmaf(v.z, v.z, s);
            s = fmaf(v.w, v.w, s);
        }
        zsq_s[tid] = s;
    }

    // ---- B chunk 0 and 1 via cp.async ----
    {
        const unsigned char* src0 = g_cb_tiles + (size_t)(h * NCHUNKS + 0) * 2 * TILE_BYTES;
        #pragma unroll
        for (int i = 0; i < 16; i++)
            cp_async16(smb + SO_B0 + (tid + i * NTHREADS) * 16, src0 + (tid + i * NTHREADS) * 16);
        cp_commit();
        const unsigned char* src1 = g_cb_tiles + (size_t)(h * NCHUNKS + 1) * 2 * TILE_BYTES;
        #pragma unroll
        for (int i = 0; i < 16; i++)
            cp_async16(smb + SO_B1 + (tid + i * NTHREADS) * 16, src1 + (tid + i * NTHREADS) * 16);
        cp_commit();
    }
    __syncthreads();

    uint32_t tmem_base;
    asm volatile("ld.shared.b32 %0, [%1];" : "=r"(tmem_base) : "r"(smb + SO_TMEMPTR));

    const uint64_t a_hi = make_desc(smb + SO_AHI);
    const uint64_t a_lo = make_desc(smb + SO_ALO);

    // ---- issue MMA chunk 0 ----
    cp_wait1();
    __syncthreads();
    FENCE_PROXY();
    if (wid == 0 && elect_one()) {
        uint64_t b_hi = make_desc(smb + SO_B0);
        uint64_t b_lo = make_desc(smb + SO_B0 + TILE_BYTES);
        uint32_t first = 0;
        #pragma unroll
        for (int pass = 0; pass < 3; pass++) {
            uint64_t ad = (pass == 2) ? a_lo : a_hi;
            uint64_t bd = (pass == 1) ? b_lo : b_hi;
            #pragma unroll
            for (int k = 0; k < 8; k++) {
                uint64_t off = (k < 4) ? (uint64_t)(k * 2) : (uint64_t)(1024 + (k - 4) * 2);
                mma_f16_ss(tmem_base, ad + off, bd + off, IDESC, first);
                first = 1;
            }
        }
        asm volatile("tcgen05.commit.cta_group::1.mbarrier::arrive::one.shared::cluster.b64 [%0];"
                     :: "r"(mbar0) : "memory");
    }

    float m1 = 3.4e38f, m2 = 3.4e38f;
    int   i1 = 0;
    const float zq2 = zsq_s[myrow];

    for (int kchunk = 0; kchunk < NCHUNKS; kchunk++) {
        const int buf = kchunk & 1;
        const uint32_t mb  = buf ? mbar1 : mbar0;
        const uint32_t mbn = buf ? mbar0 : mbar1;

        mbar_wait(mb, (kchunk >> 1) & 1);
        T05_FENCE_AFTER();

        if (kchunk + 2 < NCHUNKS) {
            const uint32_t dst = smb + (buf ? SO_B1 : SO_B0);
            const unsigned char* src = g_cb_tiles + (size_t)(h * NCHUNKS + kchunk + 2) * 2 * TILE_BYTES;
            #pragma unroll
            for (int i = 0; i < 16; i++)
                cp_async16(dst + (tid + i * NTHREADS) * 16, src + (tid + i * NTHREADS) * 16);
            cp_commit();
        }

        if (kchunk + 1 < NCHUNKS) {
            if (kchunk + 2 < NCHUNKS) cp_wait1(); else cp_wait0();
            __syncthreads();
            FENCE_PROXY();
            if (wid == 0 && elect_one()) {
                const uint32_t bbase = smb + (buf ? SO_B0 : SO_B1);
                uint64_t b_hi = make_desc(bbase);
                uint64_t b_lo = make_desc(bbase + TILE_BYTES);
                const uint32_t dtm = tmem_base + (1 - buf) * CHUNK;
                uint32_t first = 0;
                #pragma unroll
                for (int pass = 0; pass < 3; pass++) {
                    uint64_t ad = (pass == 2) ? a_lo : a_hi;
                    uint64_t bd = (pass == 1) ? b_lo : b_hi;
                    #pragma unroll
                    for (int k = 0; k < 8; k++) {
                        uint64_t off = (k < 4) ? (uint64_t)(k * 2) : (uint64_t)(1024 + (k - 4) * 2);
                        mma_f16_ss(dtm, ad + off, bd + off, IDESC, first);
                        first = 1;
                    }
                }
                asm volatile("tcgen05.commit.cta_group::1.mbarrier::arrive::one.shared::cluster.b64 [%0];"
                             :: "r"(mbn) : "memory");
            }
        }

        // ---- epilogue for chunk kchunk from D[buf] ----
        uint32_t dr[64];
        LDTM_X32(dr,      tmem_base + buf * CHUNK + wgid * 64);
        LDTM_X32(dr + 32, tmem_base + buf * CHUNK + wgid * 64 + 32);
        T05_WAIT_LD();
        T05_FENCE_BEFORE();

        float dv[64];
        const int cb0 = kchunk * CHUNK + wgid * 64;
        #pragma unroll
        for (int j = 0; j < 64; j++) {
            float t = zq2 + csq_s[cb0 + j];
            dv[j] = fmaf(-2.0f, __uint_as_float(dr[j]), t);
        }
        #pragma unroll
        for (int j = 0; j < 64; j++) {
            float v = dv[j];
            if (v < m1) { m2 = m1; m1 = v; i1 = cb0 + j; }
            else if (v < m2) { m2 = v; }
        }

        // ---- transpose passes: 4 x 32 cols through Tb[32][129] ----
        #pragma unroll
        for (int p = 0; p < 4; p++) {
            __syncthreads();
            if (wgid == (p >> 1)) {
                #pragma unroll
                for (int j2 = 0; j2 < 32; j2++) {
                    Tb[j2 * 129 + myrow] = dv[(p & 1) * 32 + j2];
                }
            }
            __syncthreads();
            const int pc = kchunk * CHUNK + p * 32;
            #pragma unroll
            for (int i = 0; i < 16; i++) {
                int r = wid + i * 8;
                float v = Tb[lane * 129 + r];
                dist_out[((size_t)(b0 + r) * N_HEADS + h) * N_CODES + pc + lane] = v;
            }
        }
        __syncthreads();
    }

    // ---- merge the two warpgroup halves per row ----
    float* mv  = Tb;
    int*   mi  = (int*)(Tb + 256);
    float* m2v = Tb + 512;
    mv [wgid * 128 + myrow] = m1;
    mi [wgid * 128 + myrow] = i1;
    m2v[wgid * 128 + myrow] = m2;
    __syncthreads();
    if (tid < TILE_B) {
        float a1 = mv[tid], b1 = mv[128 + tid];
        int   ai = mi[tid], bi = mi[128 + tid];
        float a2 = m2v[tid], b2 = m2v[128 + tid];
        float bv; int bidx; float g2;
        if (b1 < a1 || (b1 == a1 && bi < ai)) { bv = b1; bidx = bi; g2 = fminf(b2, a1); }
        else                                  { bv = a1; bidx = ai; g2 = fminf(a2, b1); }
        idxs[tid] = bidx;
        if (g2 - bv < REFINE_GAP) {
            int slot = atomicAdd(nflag, 1);
            flagl[slot] = tid;
        }
    }
    __syncthreads();

    // ---- fp64 refinement for near-tie rows ----
    const int nf = *nflag;
    float* redv = Tb + 1024;
    int*   redi = (int*)(Tb + 1280);
    for (int f = 0; f < nf; f++) {
        const int r = flagl[f];
        const float zr2 = zsq_s[r];
        const float4* zrow = (const float4*)(z + (size_t)(b0 + r) * N_EMBED + h * HD);
        float bestv = 3.4e38f;
        int   bestk = 0x7fffffff;
        #pragma unroll
        for (int kk = 0; kk < 4; kk++) {
            const int k = tid + kk * NTHREADS;
            const float4* c4 = (const float4*)(cb + ((size_t)h * N_CODES + k) * HD);
            double dot = 0.0, cs2 = 0.0;
            #pragma unroll 8
            for (int q = 0; q < HD / 4; q++) {
                float4 cv = c4[q];
                float4 zv = zrow[q];
                dot += (double)zv.x * cv.x + (double)zv.y * cv.y + (double)zv.z * cv.z + (double)zv.w * cv.w;
                cs2 += (double)cv.x * cv.x + (double)cv.y * cv.y + (double)cv.z * cv.z + (double)cv.w * cv.w;
            }
            float dotf = (float)dot;
            float csqf = (float)cs2;
            float t = zr2 + csqf;
            float d = fmaf(-2.0f, dotf, t);
            if (d < bestv || (d == bestv && k < bestk)) { bestv = d; bestk = k; }
        }
        redv[tid] = bestv;
        redi[tid] = bestk;
        __syncthreads();
        for (int s = NTHREADS / 2; s > 0; s >>= 1) {
            if (tid < s) {
                float v2 = redv[tid + s]; int k2 = redi[tid + s];
                float v1 = redv[tid];     int k1 = redi[tid];
                if (v2 < v1 || (v2 == v1 && k2 < k1)) { redv[tid] = v2; redi[tid] = k2; }
            }
            __syncthreads();
        }
        if (tid == 0) idxs[r] = redi[0];
        __syncthreads();
    }

    if (tid < TILE_B) idx_out[(size_t)(b0 + tid) * N_HEADS + h] = (float)idxs[tid];
    __syncthreads();

    const float4* cb4 = (const float4*)cb;
    float4* zq4 = (float4*)zq_out;
    #pragma unroll
    for (int s = 0; s < TILE_B * (HD / 4) / NTHREADS; s++) {
        int e = tid + s * NTHREADS;
        int r = e >> 5;
        int q = e & 31;
        int c = idxs[r];
        zq4[(size_t)(b0 + r) * (N_EMBED / 4) + h * (HD / 4) + q] =
            cb4[((size_t)h * N_CODES + c) * (HD / 4) + q];
    }

    __syncthreads();
    if (wid == 0) {
        asm volatile("tcgen05.dealloc.cta_group::1.sync.aligned.b32 %0, %1;"
                     :: "r"(tmem_base), "r"(256u));
    }
#endif // TCOK
}

// ---------------- fp32 fallback kernel (proven R3, 2446us) ----------------
#define F_TILE 128
#define F_SPITCH 132
#define F_SM_ZS    0
#define F_SM_CS    (F_SM_ZS + HD*F_SPITCH)
#define F_SM_ZSQ   (F_SM_CS + HD*F_SPITCH)
#define F_SM_CSQ   (F_SM_ZSQ + F_TILE)
#define F_SM_REDV  (F_SM_CSQ + F_TILE)
#define F_SM_REDI  (F_SM_REDV + F_TILE*16)
#define F_SM_REDV2 (F_SM_REDI + F_TILE*16)
#define F_SM_IDXS  (F_SM_REDV2 + F_TILE*16)
#define F_SM_TOTAL (F_SM_IDXS + F_TILE)
#define F_SMEM_BYTES (F_SM_TOTAL * 4)

__global__ __launch_bounds__(NTHREADS, 1)
void vq_fp32_kernel(const float* __restrict__ z, const float* __restrict__ cb,
                    float* __restrict__ out)
{
#if !TCOK
    float* zq_out   = out;
    float* idx_out  = out + ZQ_ELEMS;
    float* dist_out = out + ZQ_ELEMS + IDX_ELEMS;

    const int h  = blockIdx.y;
    const int b0 = blockIdx.x * F_TILE;
    const int tid = threadIdx.x;
    const int tx = tid & 15;
    const int ty = tid >> 4;

    extern __shared__ float smf[];
    float* zs    = smf + F_SM_ZS;
    float* cs    = smf + F_SM_CS;
    float* zsq   = smf + F_SM_ZSQ;
    float* csq   = smf + F_SM_CSQ;
    float* redv  = smf + F_SM_REDV;
    int*   redi  = (int*)(smf + F_SM_REDI);
    float* redv2 = smf + F_SM_REDV2;
    int*   idxs  = (int*)(smf + F_SM_IDXS);

    __shared__ int nflag;
    __shared__ int flaglist[F_TILE];

    #pragma unroll
    for (int s = 0; s < F_TILE * HD / NTHREADS; s++) {
        int e = tid + s * NTHREADS;
        int r = e >> 7;
        int d = e & 127;
        zs[d * F_SPITCH + r] = z[(size_t)(b0 + r) * N_EMBED + h * HD + d];
    }
    __syncthreads();
    if (tid < F_TILE) {
        float s = 0.f;
        #pragma unroll 8
        for (int k = 0; k < HD; k++) { float v = zs[k * F_SPITCH + tid]; s += v * v; }
        zsq[tid] = s;
    }
    if (tid == 0) nflag = 0;

    float m1[8], m2[8];
    int   i1[8];
    #pragma unroll
    for (int i = 0; i < 8; i++) { m1[i] = 3.4e38f; m2[i] = 3.4e38f; i1[i] = 0; }

    for (int kt = 0; kt < N_CODES / F_TILE; kt++) {
        const int cbase = kt * F_TILE;

        __syncthreads();
        #pragma unroll
        for (int s = 0; s < F_TILE * HD / NTHREADS; s++) {
            int e = tid + s * NTHREADS;
            int c = e >> 7;
            int d = e & 127;
            cs[d * F_SPITCH + c] = cb[((size_t)h * N_CODES + cbase + c) * HD + d];
        }
        __syncthreads();
        if (tid < F_TILE) {
            float s = 0.f;
            #pragma unroll 8
            for (int k = 0; k < HD; k++) { float v = cs[k * F_SPITCH + tid]; s += v * v; }
            csq[tid] = s;
        }
        __syncthreads();

        float acc[8][8];
        #pragma unroll
        for (int i = 0; i < 8; i++)
            #pragma unroll
            for (int j = 0; j < 8; j++) acc[i][j] = 0.f;

        #pragma unroll 4
        for (int k = 0; k < HD; k++) {
            const float* zrow = &zs[k * F_SPITCH];
            const float* crow = &cs[k * F_SPITCH];
            float4 a0 = *(const float4*)&zrow[ty * 8];
            float4 a1 = *(const float4*)&zrow[ty * 8 + 4];
            float4 bl = *(const float4*)&crow[tx * 4];
            float4 bh = *(const float4*)&crow[64 + tx * 4];
            float a[8] = {a0.x, a0.y, a0.z, a0.w, a1.x, a1.y, a1.z, a1.w};
            float b[8] = {bl.x, bl.y, bl.z, bl.w, bh.x, bh.y, bh.z, bh.w};
            #pragma unroll
            for (int i = 0; i < 8; i++)
                #pragma unroll
                for (int j = 0; j < 8; j++)
                    acc[i][j] += a[i] * b[j];
        }

        #pragma unroll
        for (int i = 0; i < 8; i++) {
            const int r = ty * 8 + i;
            const float zq2 = zsq[r];
            float dv[8];
            #pragma unroll
            for (int j = 0; j < 4; j++) {
                float t = zq2 + csq[tx * 4 + j];
                dv[j] = fmaf(-2.0f, acc[i][j], t);
            }
            #pragma unroll
            for (int j = 0; j < 4; j++) {
                float t = zq2 + csq[64 + tx * 4 + j];
                dv[4 + j] = fmaf(-2.0f, acc[i][4 + j], t);
            }
            float* drow = &dist_out[((size_t)(b0 + r) * N_HEADS + h) * N_CODES + cbase];
            *(float4*)&drow[tx * 4]      = make_float4(dv[0], dv[1], dv[2], dv[3]);
            *(float4*)&drow[64 + tx * 4] = make_float4(dv[4], dv[5], dv[6], dv[7]);
            #pragma unroll
            for (int j = 0; j < 8; j++) {
                int c = cbase + ((j < 4) ? (tx * 4 + j) : (64 + tx * 4 + j - 4));
                float v = dv[j];
                if (v < m1[i]) { m2[i] = m1[i]; m1[i] = v; i1[i] = c; }
                else if (v < m2[i]) { m2[i] = v; }
            }
        }
    }

    #pragma unroll
    for (int i = 0; i < 8; i++) {
        int r = ty * 8 + i;
        redv [r * 16 + tx] = m1[i];
        redi [r * 16 + tx] = i1[i];
        redv2[r * 16 + tx] = m2[i];
    }
    __syncthreads();
    if (tid < F_TILE) {
        float bv = redv[tid * 16];
        int   bi = redi[tid * 16];
        int   bt = 0;
        #pragma unroll
        for (int t = 1; t < 16; t++) {
            float v = redv[tid * 16 + t];
            int   c = redi[tid * 16 + t];
            if (v < bv || (v == bv && c < bi)) { bv = v; bi = c; bt = t; }
        }
        float g2 = redv2[tid * 16 + bt];
        #pragma unroll
        for (int t = 0; t < 16; t++) {
            if (t != bt) {
                float v = redv[tid * 16 + t];
                if (v < g2) g2 = v;
            }
        }
        idxs[tid] = bi;
        if (g2 - bv < REFINE_GAP) {
            int slot = atomicAdd(&nflag, 1);
            flaglist[slot] = tid;
        }
    }
    __syncthreads();

    const int nf = nflag;
    for (int f = 0; f < nf; f++) {
        const int r = flaglist[f];
        const float zq2 = zsq[r];
        float bestv = 3.4e38f;
        int   bestk = 0x7fffffff;
        #pragma unroll
        for (int kk = 0; kk < 4; kk++) {
            const int k = tid + kk * NTHREADS;
            const float4* c4 = (const float4*)(cb + ((size_t)h * N_CODES + k) * HD);
            double dot = 0.0, cs2 = 0.0;
            #pragma unroll 8
            for (int q = 0; q < HD / 4; q++) {
                float4 cv = c4[q];
                double c0 = (double)cv.x, c1 = (double)cv.y, c2 = (double)cv.z, c3 = (double)cv.w;
                double z0 = (double)zs[(q*4+0) * F_SPITCH + r];
                double z1 = (double)zs[(q*4+1) * F_SPITCH + r];
                double z2 = (double)zs[(q*4+2) * F_SPITCH + r];
                double z3 = (double)zs[(q*4+3) * F_SPITCH + r];
                dot += z0*c0 + z1*c1 + z2*c2 + z3*c3;
                cs2 += c0*c0 + c1*c1 + c2*c2 + c3*c3;
            }
            float dotf = (float)dot;
            float csqf = (float)cs2;
            float t = zq2 + csqf;
            float d = fmaf(-2.0f, dotf, t);
            if (d < bestv || (d == bestv && k < bestk)) { bestv = d; bestk = k; }
        }
        redv[tid] = bestv;
        redi[tid] = bestk;
        __syncthreads();
        for (int s = NTHREADS / 2; s > 0; s >>= 1) {
            if (tid < s) {
                float v2 = redv[tid + s]; int k2 = redi[tid + s];
                float v1 = redv[tid];     int k1 = redi[tid];
                if (v2 < v1 || (v2 == v1 && k2 < k1)) { redv[tid] = v2; redi[tid] = k2; }
            }
            __syncthreads();
        }
        if (tid == 0) idxs[r] = redi[0];
        __syncthreads();
    }

    if (tid < F_TILE) {
        idx_out[(size_t)(b0 + tid) * N_HEADS + h] = (float)idxs[tid];
    }
    __syncthreads();

    const float4* cb4 = (const float4*)cb;
    float4* zq4 = (float4*)zq_out;
    #pragma unroll
    for (int s = 0; s < F_TILE * (HD / 4) / NTHREADS; s++) {
        int e = tid + s * NTHREADS;
        int r = e >> 5;
        int q = e & 31;
        int c = idxs[r];
        zq4[(size_t)(b0 + r) * (N_EMBED / 4) + h * (HD / 4) + q] =
            cb4[((size_t)h * N_CODES + c) * (HD / 4) + q];
    }
#endif // !TCOK
}

// ---------------- launcher ----------------
extern "C" void kernel_launch(void* const* d_in, const int* in_sizes, int n_in,
                              void* d_out, int out_size)
{
    const float* z  = (const float*)d_in[0];   // [32768, 1024]
    const float* cb = (const float*)d_in[1];   // [8, 1024, 128]
    float* out = (float*)d_out;

    cudaFuncSetAttribute(vq_main_kernel, cudaFuncAttributeMaxDynamicSharedMemorySize, SMEM_BYTES);
    cudaFuncSetAttribute(vq_fp32_kernel, cudaFuncAttributeMaxDynamicSharedMemorySize, F_SMEM_BYTES);

    // Prep (no-ops when the tcgen05 pass is not the loaded cubin)
    prep_cb_kernel<<<N_HEADS * NCHUNKS, 256>>>(cb);
    prep_csq_kernel<<<(N_HEADS * N_CODES + 255) / 256, 256>>>(cb);

    dim3 grid(N_BATCH / TILE_B, N_HEADS);
    // Exactly one of these has a non-empty body in the loaded cubin.
    vq_main_kernel<<<grid, NTHREADS, SMEM_BYTES>>>(z, cb, out);
    vq_fp32_kernel<<<grid, NTHREADS, F_SMEM_BYTES>>>(z, cb, out);
}